// round 12
// baseline (speedup 1.0000x reference)
#include <cuda_runtime.h>
#include <cuda_bf16.h>
#include <math.h>
#include <stdint.h>

#define NPTS 32768
#define KK 32
#define DD 64
#define LOG_2PI 1.8378770664093453f

// tcgen05 is arch-SPECIFIC (sm_103a). The harness also builds a plain
// compute_103 PTX pass, which must not see tcgen05 instructions.
#if defined(__CUDA_ARCH__) && (defined(__CUDA_ARCH_FEAT_SM103_ALL) || \
    defined(__CUDA_ARCH_FEAT_SM100_ALL) || defined(__CUDA_ARCH_FEAT_SM101_ALL) || \
    defined(__CUDA_ARCH_FEAT_SM110_ALL) || defined(__CUDA_ARCH_FEAT_SM120_ALL))
#define USE_TC 1
#else
#define USE_TC 0
#endif

// ---------------- device scratch ----------------
// per-k B tile: [hi 16KB][lo 16KB]; each = 64 rows x 128 K-cols bf16,
// blocked SW128 atoms (8 rows x 64 bf16 = 1024B; atom_off = arow + acol*8)
__device__ __align__(16) unsigned char g_Bcat[KK * 32768];
__device__ __align__(16) float g_Wf[KK][64 * 68];   // fp32 W~ rows (fallback path)
__device__ float g_ck[KK];
__device__ float g_loglik[NPTS];
__device__ float g_rm[64], g_rs[64];

// ---------------- common helpers ----------------
__device__ __forceinline__ unsigned smem_u32(const void* p) {
    unsigned r;
    asm("{ .reg .u64 t; cvta.to.shared.u64 t, %1; cvt.u32.u64 %0, t; }" : "=r"(r) : "l"(p));
    return r;
}
#define MBAR_INIT(addr, cnt) \
    asm volatile("mbarrier.init.shared.b64 [%0], %1;" :: "r"(addr), "r"(cnt) : "memory")
#define MBAR_EXPECT_TX(addr, bytes) \
    asm volatile("mbarrier.arrive.expect_tx.shared.b64 _, [%0], %1;" :: "r"(addr), "r"(bytes) : "memory")
#define MBAR_WAIT(addr, parity) \
    asm volatile("{\n\t.reg .pred P;\n\tWL_%=:\n\t" \
        "mbarrier.try_wait.parity.acquire.cta.shared::cta.b64 P, [%0], %1, 0x989680;\n\t" \
        "@P bra.uni WD_%=;\n\tbra.uni WL_%=;\n\tWD_%=:\n\t}" \
        :: "r"(addr), "r"(parity) : "memory")
#define BULK_CP(dst, src, bytes, bar) \
    asm volatile("cp.async.bulk.shared::cluster.global.mbarrier::complete_tx::bytes [%0], [%1], %2, [%3];" \
        :: "r"(dst), "l"(src), "r"(bytes), "r"(bar) : "memory")
#define FENCE_PROXY()    asm volatile("fence.proxy.async.shared::cta;" ::: "memory")

#if USE_TC
// ---------------- tcgen05 helpers (sm_103a-only) ----------------
#define T_ALLOC(smaddr, n) \
    asm volatile("tcgen05.alloc.cta_group::1.sync.aligned.shared::cta.b32 [%0], %1;" :: "r"(smaddr), "r"(n) : "memory")
#define T_DEALLOC(t, n) \
    asm volatile("tcgen05.dealloc.cta_group::1.sync.aligned.b32 %0, %1;" :: "r"(t), "r"(n))
#define T_COMMIT(bar) \
    asm volatile("tcgen05.commit.cta_group::1.mbarrier::arrive::one.shared::cluster.b64 [%0];" :: "r"(bar) : "memory")
#define T_FENCE_AFTER()  asm volatile("tcgen05.fence::after_thread_sync;" ::: "memory")
#define T_FENCE_BEFORE() asm volatile("tcgen05.fence::before_thread_sync;" ::: "memory")
#define T_WAIT_LD()      asm volatile("tcgen05.wait::ld.sync.aligned;" ::: "memory")
#define T_WAIT_ST()      asm volatile("tcgen05.wait::st.sync.aligned;" ::: "memory")

#define T_LD_X32(r, tmem_addr) \
    asm volatile( \
        "tcgen05.ld.sync.aligned.32x32b.x32.b32 " \
        "{%0, %1, %2, %3, %4, %5, %6, %7, " \
        " %8, %9, %10, %11, %12, %13, %14, %15, " \
        " %16, %17, %18, %19, %20, %21, %22, %23, " \
        " %24, %25, %26, %27, %28, %29, %30, %31}, [%32];" \
        : "=r"((r)[0]),  "=r"((r)[1]),  "=r"((r)[2]),  "=r"((r)[3]), \
          "=r"((r)[4]),  "=r"((r)[5]),  "=r"((r)[6]),  "=r"((r)[7]), \
          "=r"((r)[8]),  "=r"((r)[9]),  "=r"((r)[10]), "=r"((r)[11]), \
          "=r"((r)[12]), "=r"((r)[13]), "=r"((r)[14]), "=r"((r)[15]), \
          "=r"((r)[16]), "=r"((r)[17]), "=r"((r)[18]), "=r"((r)[19]), \
          "=r"((r)[20]), "=r"((r)[21]), "=r"((r)[22]), "=r"((r)[23]), \
          "=r"((r)[24]), "=r"((r)[25]), "=r"((r)[26]), "=r"((r)[27]), \
          "=r"((r)[28]), "=r"((r)[29]), "=r"((r)[30]), "=r"((r)[31]) \
        : "r"(tmem_addr))

#define T_ST_X32(tmem_addr, r) \
    asm volatile( \
        "tcgen05.st.sync.aligned.32x32b.x32.b32 [%0], " \
        "{%1, %2, %3, %4, %5, %6, %7, %8, " \
        " %9, %10, %11, %12, %13, %14, %15, %16, " \
        " %17, %18, %19, %20, %21, %22, %23, %24, " \
        " %25, %26, %27, %28, %29, %30, %31, %32};" \
        :: "r"(tmem_addr), \
           "r"((r)[0]),  "r"((r)[1]),  "r"((r)[2]),  "r"((r)[3]), \
           "r"((r)[4]),  "r"((r)[5]),  "r"((r)[6]),  "r"((r)[7]), \
           "r"((r)[8]),  "r"((r)[9]),  "r"((r)[10]), "r"((r)[11]), \
           "r"((r)[12]), "r"((r)[13]), "r"((r)[14]), "r"((r)[15]), \
           "r"((r)[16]), "r"((r)[17]), "r"((r)[18]), "r"((r)[19]), \
           "r"((r)[20]), "r"((r)[21]), "r"((r)[22]), "r"((r)[23]), \
           "r"((r)[24]), "r"((r)[25]), "r"((r)[26]), "r"((r)[27]), \
           "r"((r)[28]), "r"((r)[29]), "r"((r)[30]), "r"((r)[31]) \
        : "memory")

#define T_ST_X8(tmem_addr, r) \
    asm volatile( \
        "tcgen05.st.sync.aligned.32x32b.x8.b32 [%0], " \
        "{%1, %2, %3, %4, %5, %6, %7, %8};" \
        :: "r"(tmem_addr), \
           "r"((r)[0]), "r"((r)[1]), "r"((r)[2]), "r"((r)[3]), \
           "r"((r)[4]), "r"((r)[5]), "r"((r)[6]), "r"((r)[7]) \
        : "memory")

// SW128 K-major smem descriptor (verified layout)
__device__ __forceinline__ uint64_t make_desc(uint32_t addr) {
    const uint64_t base = (uint64_t(2) << 61) | (uint64_t(1) << 46) |
                          (uint64_t(64) << 32) | (uint64_t(1) << 16);
    return base | ((uint64_t)(addr >> 4) & 0x3FFF);
}

// cg1 bf16 TS MMA (A in TMEM): idesc dtype F32, a/b BF16, N=64, M=128
#define MMA_IDESC 0x8100490u
__device__ __forceinline__ void mma_f16_ts(uint32_t d, uint32_t a, uint64_t b, uint32_t en) {
    asm volatile(
        "{\n\t.reg .pred p;\n\tsetp.ne.u32 p, %4, 0;\n\t"
        "tcgen05.mma.cta_group::1.kind::f16 [%0], [%1], %2, %3, {%5, %5, %5, %5}, p;\n\t}"
        :: "r"(d), "r"(a), "l"(b), "r"(MMA_IDESC), "r"(en), "r"(0u) : "memory");
}

// 15 K-steps, K=80: (Ahi,Bhi)x5 + (Alo,Bhi)x5 + (Ahi,Blo)x5
// A TMEM: step -> +8 cols (16 bf16). B desc: {0,2,4,6} in atom-col0, atom-col1 at 512 units.
__device__ __forceinline__ void issue_mma_k(uint32_t dtm, uint32_t ahi, uint32_t alo, uint64_t bhi) {
    const int acol[5] = {0, 8, 16, 24, 32};
    const int boff[5] = {0, 2, 4, 6, 512};
    uint64_t blo = bhi + 1024;                // lo half at +16384B
    uint32_t en = 0;
#pragma unroll
    for (int s = 0; s < 5; s++) { mma_f16_ts(dtm, ahi + acol[s], bhi + boff[s], en); en = 1; }
#pragma unroll
    for (int s = 0; s < 5; s++) mma_f16_ts(dtm, alo + acol[s], bhi + boff[s], 1);
#pragma unroll
    for (int s = 0; s < 5; s++) mma_f16_ts(dtm, ahi + acol[s], blo + boff[s], 1);
}
#endif  // USE_TC

// ============= setup: Sigma -> GJ inverse -> chol(Sinv)=G -> pack (bf16 + fp32) =============
extern __shared__ float dsm[];
__global__ void __launch_bounds__(512) setup_kernel(const float* __restrict__ L,
                                                    const float* __restrict__ mu,
                                                    const float* __restrict__ w) {
    float* G = dsm;                  // [64][65]: first Lt, then G = chol(Sinv)
    float* M = dsm + 64 * 65;        // [64][129] augmented [Sigma | I]
    __shared__ float colb[64];
    __shared__ float rowb[128];
    __shared__ float pivs[64];
    __shared__ float bsh[64];
    int k = blockIdx.x, tid = threadIdx.x;

    for (int i = tid; i < DD * DD; i += 512) {
        int d = i >> 6, m = i & 63;
        G[m * 65 + d] = L[(size_t)k * DD * DD + i];
    }
    __syncthreads();
    for (int i = tid; i < DD * DD; i += 512) {
        int d = i >> 6, e = i & 63;
        int mm = min(d, e);
        float s = (d == e) ? 1.0f : 0.0f;
        for (int m = 0; m <= mm; m++) s = fmaf(G[m * 65 + d], G[m * 65 + e], s);
        M[d * 129 + e] = s;
        M[d * 129 + 64 + e] = (d == e) ? 1.0f : 0.0f;
    }
    __syncthreads();
    for (int j = 0; j < DD; j++) {
        float piv = M[j * 129 + j];
        float inv = 1.0f / piv;
        if (tid < 64) colb[tid] = M[tid * 129 + j];
        if (tid < 128) rowb[tid] = M[j * 129 + tid] * inv;
        if (tid == 0) pivs[j] = piv;
        __syncthreads();
        for (int t = tid; t < DD * 128; t += 512) {
            int i = t >> 7, c = t & 127;
            float v = (i == j) ? rowb[c] : fmaf(-colb[i], rowb[c], M[i * 129 + c]);
            M[i * 129 + c] = v;
        }
        __syncthreads();
    }
    for (int i = tid; i < DD * DD; i += 512) {
        int d = i >> 6, e = i & 63;
        G[d * 65 + e] = M[d * 129 + 64 + e];
    }
    __syncthreads();
    {
        int ri = tid & 63, l8 = tid >> 6;
        for (int j = 0; j < DD; j++) {
            float piv = G[j * 65 + j];
            __syncthreads();
            float d = sqrtf(piv);
            float inv = 1.0f / d;
            if (l8 == 0 && ri > j) G[ri * 65 + j] *= inv;
            if (l8 == 0 && ri == j) G[j * 65 + j] = d;
            __syncthreads();
            if (ri > j) {
                float lv = G[ri * 65 + j];
                for (int c = j + 1 + l8; c <= ri; c += 8) G[ri * 65 + c] = fmaf(-lv, G[c * 65 + j], G[ri * 65 + c]);
            }
            __syncthreads();
        }
    }
    if (tid < 64) colb[tid] = mu[k * DD + tid];
    __syncthreads();
    {
        int j = tid >> 3, l8 = tid & 7;
        float p = 0.f;
        for (int c = l8; c < DD; c += 8)
            if (c >= j) p = fmaf(G[c * 65 + j], colb[c], p);
        p += __shfl_xor_sync(0xffffffffu, p, 1);
        p += __shfl_xor_sync(0xffffffffu, p, 2);
        p += __shfl_xor_sync(0xffffffffu, p, 4);
        if (l8 == 0) bsh[j] = p;
    }
    if (tid < 64) pivs[tid] = logf(pivs[tid]);
    __syncthreads();
    // pack W~ = [G^T | -G^T mu | 0...] hi/lo bf16 blocked-atom SW128 + fp32 copy
    for (int idx = tid; idx < 64 * 128; idx += 512) {
        int j = idx >> 7, c = idx & 127;
        float v = 0.f;
        if (c < 64) { if (c >= j) v = G[c * 65 + j]; }
        else if (c == 64) v = -bsh[j];
        __nv_bfloat16 hi = __float2bfloat16(v);
        __nv_bfloat16 lo = __float2bfloat16(v - __bfloat162float(hi));
        uint32_t byte = (uint32_t)(((j >> 3) + (c >> 6) * 8) * 1024 + (j & 7) * 128 + (c & 63) * 2);
        uint32_t sw = byte ^ ((byte >> 3) & 0x70);
        *(__nv_bfloat16*)(g_Bcat + (size_t)k * 32768 + sw) = hi;
        *(__nv_bfloat16*)(g_Bcat + (size_t)k * 32768 + 16384 + sw) = lo;
        if (c < 68) g_Wf[k][j * 68 + c] = v;
    }
    if (tid < 32) {
        float ldv = pivs[tid] + pivs[tid + 32];
        for (int o = 16; o; o >>= 1) ldv += __shfl_xor_sync(0xffffffffu, ldv, o);
        float wv = w[tid];
        float mxw = wv;
        for (int o = 16; o; o >>= 1) mxw = fmaxf(mxw, __shfl_xor_sync(0xffffffffu, mxw, o));
        float se = __expf(wv - mxw);
        for (int o = 16; o; o >>= 1) se += __shfl_xor_sync(0xffffffffu, se, o);
        float lgk = __shfl_sync(0xffffffffu, wv - (mxw + logf(se)), k);
        if (tid == 0) g_ck[k] = lgk - 0.5f * (DD * LOG_2PI + ldv);
    }
}

// ============= main: 128-point tile; TS-mode tcgen05 (A in TMEM) =============
// TMEM map: A_hi cols 0..39, A_lo cols 64..103, D0 128..191, D1 192..255 (alloc 256)
// dyn smem: [B0 32KB][B1 32KB] (+1KB align slack)
__global__ void main_kernel(const float* __restrict__ X) {
#if USE_TC
    extern __shared__ char msm[];
    __shared__ unsigned long long s_bar[4];   // [0,1] mma_done, [2,3] B_full
    __shared__ uint32_t s_tmem;
    __shared__ float s_ck[KK];

    uint32_t raw = smem_u32(msm);
    uint32_t sbase = (raw + 1023u) & ~1023u;
    int tx = threadIdx.x, wid = tx >> 5;

    if (wid == 0) T_ALLOC(smem_u32(&s_tmem), 256);
    if (tx == 0)
        for (int i = 0; i < 4; i++) MBAR_INIT(smem_u32(&s_bar[i]), 1);
    if (tx < KK) s_ck[tx] = g_ck[tx];
    __syncthreads();

    uint32_t tmem;
    asm volatile("ld.shared.b32 %0, [%1];" : "=r"(tmem) : "r"(smem_u32(&s_tmem)));
    uint32_t warp_off = (uint32_t)(wid << 21);

    // kick off B0/B1 bulk copies early (overlap with A->TMEM stores)
    if (tx == 0) {
#pragma unroll
        for (int c = 0; c < 2; c++) {
            unsigned bf = smem_u32(&s_bar[2 + c]);
            MBAR_EXPECT_TX(bf, 32768u);
            BULK_CP(sbase + c * 32768u, g_Bcat + (size_t)c * 32768u, 32768u, bf);
        }
    }

    // build A in TMEM: row r = tx; hi pairs cols 0..39, lo pairs cols 64..103
    {
        const float4* xs = (const float4*)(X + ((size_t)blockIdx.x * 128 + tx) * DD);
        uint32_t h[40], l[40];
#pragma unroll
        for (int i = 0; i < 16; i++) {
            float4 v = xs[i];
            float x0 = v.x, x1 = v.y, x2 = v.z, x3 = v.w;
            __nv_bfloat162 hp0, hp1, lp0, lp1;
            hp0.x = __float2bfloat16(x0); hp0.y = __float2bfloat16(x1);
            hp1.x = __float2bfloat16(x2); hp1.y = __float2bfloat16(x3);
            lp0.x = __float2bfloat16(x0 - __bfloat162float(hp0.x));
            lp0.y = __float2bfloat16(x1 - __bfloat162float(hp0.y));
            lp1.x = __float2bfloat16(x2 - __bfloat162float(hp1.x));
            lp1.y = __float2bfloat16(x3 - __bfloat162float(hp1.y));
            h[2 * i]     = *(uint32_t*)&hp0;
            h[2 * i + 1] = *(uint32_t*)&hp1;
            l[2 * i]     = *(uint32_t*)&lp0;
            l[2 * i + 1] = *(uint32_t*)&lp1;
        }
        {
            __nv_bfloat162 one; one.x = __float2bfloat16(1.0f); one.y = __float2bfloat16(0.0f);
            h[32] = *(uint32_t*)&one;
            l[32] = 0u;
#pragma unroll
            for (int i = 33; i < 40; i++) { h[i] = 0u; l[i] = 0u; }
        }
        T_ST_X32(tmem + 0 + warp_off, h);
        T_ST_X8(tmem + 32 + warp_off, h + 32);
        T_ST_X32(tmem + 64 + warp_off, l);
        T_ST_X8(tmem + 96 + warp_off, l + 32);
        T_WAIT_ST();
    }
    T_FENCE_BEFORE();
    __syncthreads();

    // prologue: wait B0, issue MMA(0) -> D0, commit to bar0
    if (tx == 0) {
        T_FENCE_AFTER();
        MBAR_WAIT(smem_u32(&s_bar[2]), 0);
        issue_mma_k(tmem + 128, tmem + 0, tmem + 64, make_desc(sbase));
        T_COMMIT(smem_u32(&s_bar[0]));
    }

    float mx = -INFINITY, sm = 0.f;
#pragma unroll 1
    for (int k = 0; k < KK; k++) {
        int buf = k & 1;
        MBAR_WAIT(smem_u32(&s_bar[buf]), (k >> 1) & 1);
        T_FENCE_AFTER();
        if (tx == 0) {
            if (k + 2 < KK) {
                unsigned bf = smem_u32(&s_bar[2 + buf]);
                MBAR_EXPECT_TX(bf, 32768u);
                BULK_CP(sbase + buf * 32768u, g_Bcat + (size_t)(k + 2) * 32768u, 32768u, bf);
            }
            if (k + 1 < KK) {
                int nb = (k + 1) & 1;
                MBAR_WAIT(smem_u32(&s_bar[2 + nb]), ((k + 1) >> 1) & 1);
                issue_mma_k(tmem + 128 + nb * 64, tmem + 0, tmem + 64,
                            make_desc(sbase + nb * 32768u));
                T_COMMIT(smem_u32(&s_bar[nb]));
            }
        }
        // epilogue: maha = sum_j z_j^2 over 64 N-columns
        uint32_t dr[64];
        T_LD_X32(dr, tmem + 128 + buf * 64);
        T_LD_X32(dr + 32, tmem + 128 + buf * 64 + 32);
        T_WAIT_LD();
        float m0 = 0.f, m1 = 0.f, m2 = 0.f, m3 = 0.f;
#pragma unroll
        for (int j = 0; j < 16; j++) {
            float a = __uint_as_float(dr[4 * j]);
            float b = __uint_as_float(dr[4 * j + 1]);
            float c = __uint_as_float(dr[4 * j + 2]);
            float d = __uint_as_float(dr[4 * j + 3]);
            m0 = fmaf(a, a, m0);
            m1 = fmaf(b, b, m1);
            m2 = fmaf(c, c, m2);
            m3 = fmaf(d, d, m3);
        }
        float logp = s_ck[k] - 0.5f * ((m0 + m1) + (m2 + m3));
        if (logp > mx) { sm = fmaf(sm, __expf(mx - logp), 1.0f); mx = logp; }
        else           { sm += __expf(logp - mx); }
        T_FENCE_BEFORE();
        __syncthreads();
    }

    g_loglik[blockIdx.x * 128 + tx] = mx + logf(sm);
    __syncthreads();
    if (wid == 0) T_DEALLOC(tmem, 256);
#else
    // ---------- generic scalar fallback: maha = || W~ x~ ||^2 ----------
    extern __shared__ char msm[];
    float* sW = (float*)msm;                  // [64*68] fp32 W~ for current k
    __shared__ float s_ck[KK];
    int tx = threadIdx.x;
    if (tx < KK) s_ck[tx] = g_ck[tx];

    float xt[65];
    {
        const float4* xs = (const float4*)(X + ((size_t)blockIdx.x * 128 + tx) * DD);
#pragma unroll
        for (int i = 0; i < 16; i++) {
            float4 v = xs[i];
            xt[4 * i] = v.x; xt[4 * i + 1] = v.y; xt[4 * i + 2] = v.z; xt[4 * i + 3] = v.w;
        }
        xt[64] = 1.0f;
    }

    float mx = -INFINITY, sm = 0.f;
#pragma unroll 1
    for (int k = 0; k < KK; k++) {
        __syncthreads();
        const float4* src = (const float4*)g_Wf[k];
        for (int i = tx; i < 64 * 68 / 4; i += 128) ((float4*)sW)[i] = src[i];
        __syncthreads();
        float maha = 0.f;
        for (int j = 0; j < 64; j++) {
            const float* row = sW + j * 68;
            float z = 0.f;
#pragma unroll
            for (int c = 0; c < 65; c++) z = fmaf(row[c], xt[c], z);
            maha = fmaf(z, z, maha);
        }
        float logp = s_ck[k] - 0.5f * maha;
        if (logp > mx) { sm = fmaf(sm, __expf(mx - logp), 1.0f); mx = logp; }
        else           { sm += __expf(logp - mx); }
    }
    g_loglik[blockIdx.x * 128 + tx] = mx + logf(sm);
#endif
}

// ============= two-stage final reduce: -logsumexp over N =============
__global__ void reduceA_kernel() {
    __shared__ float red[8];
    int b = blockIdx.x, tid = threadIdx.x;
    const float* src = g_loglik + b * 512;
    float v0 = src[tid], v1 = src[tid + 256];
    float m = fmaxf(v0, v1);
    for (int o = 16; o; o >>= 1) m = fmaxf(m, __shfl_xor_sync(0xffffffffu, m, o));
    if ((tid & 31) == 0) red[tid >> 5] = m;
    __syncthreads();
    if (tid < 8) {
        float t = red[tid];
        for (int o = 4; o; o >>= 1) t = fmaxf(t, __shfl_xor_sync(0xffu, t, o));
        red[tid] = t;
    }
    __syncthreads();
    float M = red[0];
    float s = __expf(v0 - M) + __expf(v1 - M);
    for (int o = 16; o; o >>= 1) s += __shfl_xor_sync(0xffffffffu, s, o);
    __syncthreads();
    if ((tid & 31) == 0) red[tid >> 5] = s;
    __syncthreads();
    if (tid == 0) {
        float t = 0.f;
        for (int i = 0; i < 8; i++) t += red[i];
        g_rm[b] = M;
        g_rs[b] = t;
    }
}

__global__ void reduceB_kernel(float* __restrict__ out) {
    int lid = threadIdx.x;
    float m0 = g_rm[lid], m1 = g_rm[lid + 32];
    float m = fmaxf(m0, m1);
    for (int o = 16; o; o >>= 1) m = fmaxf(m, __shfl_xor_sync(0xffffffffu, m, o));
    float s = g_rs[lid] * __expf(m0 - m) + g_rs[lid + 32] * __expf(m1 - m);
    for (int o = 16; o; o >>= 1) s += __shfl_xor_sync(0xffffffffu, s, o);
    if (lid == 0) out[0] = -(m + logf(s));
}

// ---------------- launch ----------------
extern "C" void kernel_launch(void* const* d_in, const int* in_sizes, int n_in,
                              void* d_out, int out_size) {
    const float* X  = (const float*)d_in[0];
    const float* mu = (const float*)d_in[1];
    const float* L  = (const float*)d_in[2];
    const float* w  = (const float*)d_in[3];
    float* out = (float*)d_out;

    static int attr_done = 0;
    if (!attr_done) {
        cudaFuncSetAttribute(setup_kernel, cudaFuncAttributeMaxDynamicSharedMemorySize, 49664);
        cudaFuncSetAttribute(main_kernel, cudaFuncAttributeMaxDynamicSharedMemorySize, 66560);
        attr_done = 1;
    }

    setup_kernel<<<KK, 512, 49664>>>(L, mu, w);
    main_kernel<<<NPTS / 128, 128, 66560>>>(X);
    reduceA_kernel<<<64, 256>>>();
    reduceB_kernel<<<1, 32>>>(out);
}

// round 13
// speedup vs baseline: 1.8325x; 1.8325x over previous
#include <cuda_runtime.h>
#include <cuda_bf16.h>
#include <math.h>
#include <stdint.h>

#define NPTS 32768
#define KK 32
#define DD 64
#define LOG_2PI 1.8378770664093453f

// tcgen05 is arch-SPECIFIC (sm_103a). The harness also builds a plain
// compute_103 PTX pass, which must not see tcgen05 instructions.
#if defined(__CUDA_ARCH__) && (defined(__CUDA_ARCH_FEAT_SM103_ALL) || \
    defined(__CUDA_ARCH_FEAT_SM100_ALL) || defined(__CUDA_ARCH_FEAT_SM101_ALL) || \
    defined(__CUDA_ARCH_FEAT_SM110_ALL) || defined(__CUDA_ARCH_FEAT_SM120_ALL))
#define USE_TC 1
#else
#define USE_TC 0
#endif

// ---------------- device scratch ----------------
// per-k B tile: [hi 16KB][lo 16KB]; each = 64 rows x 128 K-cols bf16,
// blocked SW128 atoms (8 rows x 64 bf16 = 1024B; atom_off = arow + acol*8)
__device__ __align__(16) unsigned char g_Bcat[KK * 32768];
__device__ __align__(16) float g_Wf[KK][64 * 68];   // fp32 W~ rows (fallback path)
__device__ float g_ck[KK];
__device__ float g_rm[128], g_rs[128];

// ---------------- common helpers ----------------
__device__ __forceinline__ unsigned smem_u32(const void* p) {
    unsigned r;
    asm("{ .reg .u64 t; cvta.to.shared.u64 t, %1; cvt.u32.u64 %0, t; }" : "=r"(r) : "l"(p));
    return r;
}
#define MBAR_INIT(addr, cnt) \
    asm volatile("mbarrier.init.shared.b64 [%0], %1;" :: "r"(addr), "r"(cnt) : "memory")
#define MBAR_EXPECT_TX(addr, bytes) \
    asm volatile("mbarrier.arrive.expect_tx.shared.b64 _, [%0], %1;" :: "r"(addr), "r"(bytes) : "memory")
#define MBAR_ARRIVE(addr) \
    asm volatile("mbarrier.arrive.shared.b64 _, [%0];" :: "r"(addr) : "memory")
#define MBAR_WAIT(addr, parity) \
    asm volatile("{\n\t.reg .pred P;\n\tWL_%=:\n\t" \
        "mbarrier.try_wait.parity.acquire.cta.shared::cta.b64 P, [%0], %1, 0x989680;\n\t" \
        "@P bra.uni WD_%=;\n\tbra.uni WL_%=;\n\tWD_%=:\n\t}" \
        :: "r"(addr), "r"(parity) : "memory")
#define BULK_CP(dst, src, bytes, bar) \
    asm volatile("cp.async.bulk.shared::cluster.global.mbarrier::complete_tx::bytes [%0], [%1], %2, [%3];" \
        :: "r"(dst), "l"(src), "r"(bytes), "r"(bar) : "memory")

#if USE_TC
// ---------------- tcgen05 helpers (sm_103a-only) ----------------
#define T_ALLOC(smaddr, n) \
    asm volatile("tcgen05.alloc.cta_group::1.sync.aligned.shared::cta.b32 [%0], %1;" :: "r"(smaddr), "r"(n) : "memory")
#define T_DEALLOC(t, n) \
    asm volatile("tcgen05.dealloc.cta_group::1.sync.aligned.b32 %0, %1;" :: "r"(t), "r"(n))
#define T_COMMIT(bar) \
    asm volatile("tcgen05.commit.cta_group::1.mbarrier::arrive::one.shared::cluster.b64 [%0];" :: "r"(bar) : "memory")
#define T_FENCE_AFTER()  asm volatile("tcgen05.fence::after_thread_sync;" ::: "memory")
#define T_FENCE_BEFORE() asm volatile("tcgen05.fence::before_thread_sync;" ::: "memory")
#define T_WAIT_LD()      asm volatile("tcgen05.wait::ld.sync.aligned;" ::: "memory")
#define T_WAIT_ST()      asm volatile("tcgen05.wait::st.sync.aligned;" ::: "memory")

#define T_LD_X32(r, tmem_addr) \
    asm volatile( \
        "tcgen05.ld.sync.aligned.32x32b.x32.b32 " \
        "{%0, %1, %2, %3, %4, %5, %6, %7, " \
        " %8, %9, %10, %11, %12, %13, %14, %15, " \
        " %16, %17, %18, %19, %20, %21, %22, %23, " \
        " %24, %25, %26, %27, %28, %29, %30, %31}, [%32];" \
        : "=r"((r)[0]),  "=r"((r)[1]),  "=r"((r)[2]),  "=r"((r)[3]), \
          "=r"((r)[4]),  "=r"((r)[5]),  "=r"((r)[6]),  "=r"((r)[7]), \
          "=r"((r)[8]),  "=r"((r)[9]),  "=r"((r)[10]), "=r"((r)[11]), \
          "=r"((r)[12]), "=r"((r)[13]), "=r"((r)[14]), "=r"((r)[15]), \
          "=r"((r)[16]), "=r"((r)[17]), "=r"((r)[18]), "=r"((r)[19]), \
          "=r"((r)[20]), "=r"((r)[21]), "=r"((r)[22]), "=r"((r)[23]), \
          "=r"((r)[24]), "=r"((r)[25]), "=r"((r)[26]), "=r"((r)[27]), \
          "=r"((r)[28]), "=r"((r)[29]), "=r"((r)[30]), "=r"((r)[31]) \
        : "r"(tmem_addr))

#define T_ST_X32(tmem_addr, r) \
    asm volatile( \
        "tcgen05.st.sync.aligned.32x32b.x32.b32 [%0], " \
        "{%1, %2, %3, %4, %5, %6, %7, %8, " \
        " %9, %10, %11, %12, %13, %14, %15, %16, " \
        " %17, %18, %19, %20, %21, %22, %23, %24, " \
        " %25, %26, %27, %28, %29, %30, %31, %32};" \
        :: "r"(tmem_addr), \
           "r"((r)[0]),  "r"((r)[1]),  "r"((r)[2]),  "r"((r)[3]), \
           "r"((r)[4]),  "r"((r)[5]),  "r"((r)[6]),  "r"((r)[7]), \
           "r"((r)[8]),  "r"((r)[9]),  "r"((r)[10]), "r"((r)[11]), \
           "r"((r)[12]), "r"((r)[13]), "r"((r)[14]), "r"((r)[15]), \
           "r"((r)[16]), "r"((r)[17]), "r"((r)[18]), "r"((r)[19]), \
           "r"((r)[20]), "r"((r)[21]), "r"((r)[22]), "r"((r)[23]), \
           "r"((r)[24]), "r"((r)[25]), "r"((r)[26]), "r"((r)[27]), \
           "r"((r)[28]), "r"((r)[29]), "r"((r)[30]), "r"((r)[31]) \
        : "memory")

#define T_ST_X8(tmem_addr, r) \
    asm volatile( \
        "tcgen05.st.sync.aligned.32x32b.x8.b32 [%0], " \
        "{%1, %2, %3, %4, %5, %6, %7, %8};" \
        :: "r"(tmem_addr), \
           "r"((r)[0]), "r"((r)[1]), "r"((r)[2]), "r"((r)[3]), \
           "r"((r)[4]), "r"((r)[5]), "r"((r)[6]), "r"((r)[7]) \
        : "memory")

// SW128 K-major smem descriptor (verified layout)
__device__ __forceinline__ uint64_t make_desc(uint32_t addr) {
    const uint64_t base = (uint64_t(2) << 61) | (uint64_t(1) << 46) |
                          (uint64_t(64) << 32) | (uint64_t(1) << 16);
    return base | ((uint64_t)(addr >> 4) & 0x3FFF);
}

// cg1 bf16 TS MMA (A in TMEM): idesc dtype F32, a/b BF16, N=64, M=128
#define MMA_IDESC 0x8100490u
__device__ __forceinline__ void mma_f16_ts(uint32_t d, uint32_t a, uint64_t b, uint32_t en) {
    asm volatile(
        "{\n\t.reg .pred p;\n\tsetp.ne.u32 p, %4, 0;\n\t"
        "tcgen05.mma.cta_group::1.kind::f16 [%0], [%1], %2, %3, {%5, %5, %5, %5}, p;\n\t}"
        :: "r"(d), "r"(a), "l"(b), "r"(MMA_IDESC), "r"(en), "r"(0u) : "memory");
}

// 15 K-steps, K=80: (Ahi,Bhi)x5 + (Alo,Bhi)x5 + (Ahi,Blo)x5
__device__ __forceinline__ void issue_mma_k(uint32_t dtm, uint32_t ahi, uint32_t alo, uint64_t bhi) {
    const int acol[5] = {0, 8, 16, 24, 32};
    const int boff[5] = {0, 2, 4, 6, 512};
    uint64_t blo = bhi + 1024;                // lo half at +16384B
    uint32_t en = 0;
#pragma unroll
    for (int s = 0; s < 5; s++) { mma_f16_ts(dtm, ahi + acol[s], bhi + boff[s], en); en = 1; }
#pragma unroll
    for (int s = 0; s < 5; s++) mma_f16_ts(dtm, alo + acol[s], bhi + boff[s], 1);
#pragma unroll
    for (int s = 0; s < 5; s++) mma_f16_ts(dtm, ahi + acol[s], blo + boff[s], 1);
}
#endif  // USE_TC

// ============= setup: Sigma -> GJ inverse -> chol(Sinv)=G -> pack (bf16 + fp32) =============
extern __shared__ float dsm[];
__global__ void __launch_bounds__(512) setup_kernel(const float* __restrict__ L,
                                                    const float* __restrict__ mu,
                                                    const float* __restrict__ w) {
    float* G = dsm;                  // [64][65]: first Lt, then G = chol(Sinv)
    float* M = dsm + 64 * 65;        // [64][129] augmented [Sigma | I]
    __shared__ float colb[64];
    __shared__ float rowb[128];
    __shared__ float pivs[64];
    __shared__ float bsh[64];
    int k = blockIdx.x, tid = threadIdx.x;

    for (int i = tid; i < DD * DD; i += 512) {
        int d = i >> 6, m = i & 63;
        G[m * 65 + d] = L[(size_t)k * DD * DD + i];
    }
    __syncthreads();
    for (int i = tid; i < DD * DD; i += 512) {
        int d = i >> 6, e = i & 63;
        int mm = min(d, e);
        float s = (d == e) ? 1.0f : 0.0f;
        for (int m = 0; m <= mm; m++) s = fmaf(G[m * 65 + d], G[m * 65 + e], s);
        M[d * 129 + e] = s;
        M[d * 129 + 64 + e] = (d == e) ? 1.0f : 0.0f;
    }
    __syncthreads();
    for (int j = 0; j < DD; j++) {
        float piv = M[j * 129 + j];
        float inv = 1.0f / piv;
        if (tid < 64) colb[tid] = M[tid * 129 + j];
        if (tid < 128) rowb[tid] = M[j * 129 + tid] * inv;
        if (tid == 0) pivs[j] = piv;
        __syncthreads();
        for (int t = tid; t < DD * 128; t += 512) {
            int i = t >> 7, c = t & 127;
            float v = (i == j) ? rowb[c] : fmaf(-colb[i], rowb[c], M[i * 129 + c]);
            M[i * 129 + c] = v;
        }
        __syncthreads();
    }
    for (int i = tid; i < DD * DD; i += 512) {
        int d = i >> 6, e = i & 63;
        G[d * 65 + e] = M[d * 129 + 64 + e];
    }
    __syncthreads();
    {
        int ri = tid & 63, l8 = tid >> 6;
        for (int j = 0; j < DD; j++) {
            float piv = G[j * 65 + j];
            __syncthreads();
            float d = sqrtf(piv);
            float inv = 1.0f / d;
            if (l8 == 0 && ri > j) G[ri * 65 + j] *= inv;
            if (l8 == 0 && ri == j) G[j * 65 + j] = d;
            __syncthreads();
            if (ri > j) {
                float lv = G[ri * 65 + j];
                for (int c = j + 1 + l8; c <= ri; c += 8) G[ri * 65 + c] = fmaf(-lv, G[c * 65 + j], G[ri * 65 + c]);
            }
            __syncthreads();
        }
    }
    if (tid < 64) colb[tid] = mu[k * DD + tid];
    __syncthreads();
    {
        int j = tid >> 3, l8 = tid & 7;
        float p = 0.f;
        for (int c = l8; c < DD; c += 8)
            if (c >= j) p = fmaf(G[c * 65 + j], colb[c], p);
        p += __shfl_xor_sync(0xffffffffu, p, 1);
        p += __shfl_xor_sync(0xffffffffu, p, 2);
        p += __shfl_xor_sync(0xffffffffu, p, 4);
        if (l8 == 0) bsh[j] = p;
    }
    if (tid < 64) pivs[tid] = logf(pivs[tid]);
    __syncthreads();
    // pack W~ = [G^T | -G^T mu | 0...] hi/lo bf16 blocked-atom SW128 + fp32 copy
    for (int idx = tid; idx < 64 * 128; idx += 512) {
        int j = idx >> 7, c = idx & 127;
        float v = 0.f;
        if (c < 64) { if (c >= j) v = G[c * 65 + j]; }
        else if (c == 64) v = -bsh[j];
        __nv_bfloat16 hi = __float2bfloat16(v);
        __nv_bfloat16 lo = __float2bfloat16(v - __bfloat162float(hi));
        uint32_t byte = (uint32_t)(((j >> 3) + (c >> 6) * 8) * 1024 + (j & 7) * 128 + (c & 63) * 2);
        uint32_t sw = byte ^ ((byte >> 3) & 0x70);
        *(__nv_bfloat16*)(g_Bcat + (size_t)k * 32768 + sw) = hi;
        *(__nv_bfloat16*)(g_Bcat + (size_t)k * 32768 + 16384 + sw) = lo;
        if (c < 68) g_Wf[k][j * 68 + c] = v;
    }
    if (tid < 32) {
        float ldv = pivs[tid] + pivs[tid + 32];
        for (int o = 16; o; o >>= 1) ldv += __shfl_xor_sync(0xffffffffu, ldv, o);
        float wv = w[tid];
        float mxw = wv;
        for (int o = 16; o; o >>= 1) mxw = fmaxf(mxw, __shfl_xor_sync(0xffffffffu, mxw, o));
        float se = __expf(wv - mxw);
        for (int o = 16; o; o >>= 1) se += __shfl_xor_sync(0xffffffffu, se, o);
        float lgk = __shfl_sync(0xffffffffu, wv - (mxw + logf(se)), k);
        if (tid == 0) g_ck[k] = lgk - 0.5f * (DD * LOG_2PI + ldv);
    }
}

// ============= main: 256 points/CTA (2 MMA tiles), warp-specialized producer =============
// TMEM (alloc 512): A0hi 0..39, A0lo 40..79, A1hi 80..119, A1lo 120..159,
//                   D(g,b) = 160 + g*128 + b*64  (2 tiles x double-buffered N=64)
// dyn smem: 3 x 32KB B ring (+1KB align)
// barriers: s_bar[0,1]=mma_done(cnt 1), [2,3]=cons(cnt 8), [4,5,6]=bfull(cnt 1)
__global__ void __launch_bounds__(288, 1) main_kernel(const float* __restrict__ X) {
#if USE_TC
    extern __shared__ char msm[];
    __shared__ unsigned long long s_bar[7];
    __shared__ uint32_t s_tmem;
    __shared__ float s_ck[KK];
    __shared__ float s_wm[9], s_ws[9];

    uint32_t raw = smem_u32(msm);
    uint32_t sbase = (raw + 1023u) & ~1023u;
    int tx = threadIdx.x, wid = tx >> 5, lane = tx & 31;

    if (wid == 0) T_ALLOC(smem_u32(&s_tmem), 512);
    if (tx == 0) {
        MBAR_INIT(smem_u32(&s_bar[0]), 1);
        MBAR_INIT(smem_u32(&s_bar[1]), 1);
        MBAR_INIT(smem_u32(&s_bar[2]), 8);
        MBAR_INIT(smem_u32(&s_bar[3]), 8);
        MBAR_INIT(smem_u32(&s_bar[4]), 1);
        MBAR_INIT(smem_u32(&s_bar[5]), 1);
        MBAR_INIT(smem_u32(&s_bar[6]), 1);
    }
    if (tx < KK) s_ck[tx] = g_ck[tx];
    __syncthreads();

    uint32_t tmem;
    asm volatile("ld.shared.b32 %0, [%1];" : "=r"(tmem) : "r"(smem_u32(&s_tmem)));

    // producer: kick off B ring prologue copies (k=0,1,2) immediately
    if (tx == 256) {
#pragma unroll
        for (int q = 0; q < 3; q++) {
            unsigned bf = smem_u32(&s_bar[4 + q]);
            MBAR_EXPECT_TX(bf, 32768u);
            BULK_CP(sbase + q * 32768u, g_Bcat + (size_t)q * 32768u, 32768u, bf);
        }
    }

    // consumers: build A (both tiles) in TMEM
    if (tx < 256) {
        int g = tx >> 7, gtx = tx & 127;
        const float4* xs = (const float4*)(X + ((size_t)blockIdx.x * 256 + g * 128 + gtx) * DD);
        uint32_t warp_off = (uint32_t)((gtx >> 5) << 21);
        uint32_t h[40], l[40];
#pragma unroll
        for (int i = 0; i < 16; i++) {
            float4 v = xs[i];
            float x0 = v.x, x1 = v.y, x2 = v.z, x3 = v.w;
            __nv_bfloat162 hp0, hp1, lp0, lp1;
            hp0.x = __float2bfloat16(x0); hp0.y = __float2bfloat16(x1);
            hp1.x = __float2bfloat16(x2); hp1.y = __float2bfloat16(x3);
            lp0.x = __float2bfloat16(x0 - __bfloat162float(hp0.x));
            lp0.y = __float2bfloat16(x1 - __bfloat162float(hp0.y));
            lp1.x = __float2bfloat16(x2 - __bfloat162float(hp1.x));
            lp1.y = __float2bfloat16(x3 - __bfloat162float(hp1.y));
            h[2 * i]     = *(uint32_t*)&hp0;
            h[2 * i + 1] = *(uint32_t*)&hp1;
            l[2 * i]     = *(uint32_t*)&lp0;
            l[2 * i + 1] = *(uint32_t*)&lp1;
        }
        {
            __nv_bfloat162 one; one.x = __float2bfloat16(1.0f); one.y = __float2bfloat16(0.0f);
            h[32] = *(uint32_t*)&one;
            l[32] = 0u;
#pragma unroll
            for (int i = 33; i < 40; i++) { h[i] = 0u; l[i] = 0u; }
        }
        uint32_t abase = tmem + (uint32_t)(g * 80);
        T_ST_X32(abase + 0 + warp_off, h);
        T_ST_X8(abase + 32 + warp_off, h + 32);
        T_ST_X32(abase + 40 + warp_off, l);
        T_ST_X8(abase + 72 + warp_off, l + 32);
        T_WAIT_ST();
        T_FENCE_BEFORE();
    }
    __syncthreads();    // A ready in TMEM for producer's MMAs

    // ---------------- producer warp: MMA issue + B prefetch ----------------
    if (tx == 256) {
        T_FENCE_AFTER();
#pragma unroll 1
        for (int k = 0; k < KK; k++) {
            int b = k & 1;
            int q = k - (k / 3) * 3;
            MBAR_WAIT(smem_u32(&s_bar[4 + q]), (k / 3) & 1);             // B(k) in smem
            if (k >= 2) MBAR_WAIT(smem_u32(&s_bar[2 + b]), ((k - 2) >> 1) & 1);  // D[b] free
            uint64_t bd = make_desc(sbase + q * 32768u);
            issue_mma_k(tmem + 160 + b * 64, tmem + 0,  tmem + 40,  bd);  // tile 0
            issue_mma_k(tmem + 288 + b * 64, tmem + 80, tmem + 120, bd);  // tile 1
            T_COMMIT(smem_u32(&s_bar[b]));
            if (k + 3 < KK) {
                MBAR_WAIT(smem_u32(&s_bar[b]), (k >> 1) & 1);            // MMA(k) done -> B[q] free
                unsigned bf = smem_u32(&s_bar[4 + q]);
                MBAR_EXPECT_TX(bf, 32768u);
                BULK_CP(sbase + q * 32768u, g_Bcat + (size_t)(k + 3) * 32768u, 32768u, bf);
            }
        }
    }

    // ---------------- consumer warps: epilogue + online LSE ----------------
    float mx = -INFINITY, sm = 0.f;
    if (tx < 256) {
        int g = tx >> 7;
        uint32_t dbase = tmem + 160 + (uint32_t)(g * 128);
#pragma unroll 1
        for (int k = 0; k < KK; k++) {
            int b = k & 1;
            MBAR_WAIT(smem_u32(&s_bar[b]), (k >> 1) & 1);
            T_FENCE_AFTER();
            uint32_t dr[64];
            T_LD_X32(dr, dbase + b * 64);
            T_LD_X32(dr + 32, dbase + b * 64 + 32);
            T_WAIT_LD();
            if (lane == 0) MBAR_ARRIVE(smem_u32(&s_bar[2 + b]));   // D reads retired (warp-collective)
            float m0 = 0.f, m1 = 0.f, m2 = 0.f, m3 = 0.f;
#pragma unroll
            for (int j = 0; j < 16; j++) {
                float a = __uint_as_float(dr[4 * j]);
                float b2 = __uint_as_float(dr[4 * j + 1]);
                float c = __uint_as_float(dr[4 * j + 2]);
                float d = __uint_as_float(dr[4 * j + 3]);
                m0 = fmaf(a, a, m0);
                m1 = fmaf(b2, b2, m1);
                m2 = fmaf(c, c, m2);
                m3 = fmaf(d, d, m3);
            }
            float logp = s_ck[k] - 0.5f * ((m0 + m1) + (m2 + m3));
            if (logp > mx) { sm = fmaf(sm, __expf(mx - logp), 1.0f); mx = logp; }
            else           { sm += __expf(logp - mx); }
        }
    }

    // block LSE reduce -> per-CTA (M, S)
    if (tx < 256) {
#pragma unroll
        for (int o = 16; o; o >>= 1) {
            float m2 = __shfl_xor_sync(0xffffffffu, mx, o);
            float s2 = __shfl_xor_sync(0xffffffffu, sm, o);
            float M = fmaxf(mx, m2);
            sm = sm * __expf(mx - M) + s2 * __expf(m2 - M);
            mx = M;
        }
        if (lane == 0) { s_wm[wid] = mx; s_ws[wid] = sm; }
    }
    __syncthreads();
    if (tx < 8) {
        float m = s_wm[tx], s = s_ws[tx];
#pragma unroll
        for (int o = 4; o; o >>= 1) {
            float m2 = __shfl_xor_sync(0xffu, m, o);
            float s2 = __shfl_xor_sync(0xffu, s, o);
            float M = fmaxf(m, m2);
            s = s * __expf(m - M) + s2 * __expf(m2 - M);
            m = M;
        }
        if (tx == 0) { g_rm[blockIdx.x] = m; g_rs[blockIdx.x] = s; }
    }
    __syncthreads();
    if (wid == 0) T_DEALLOC(tmem, 512);
#else
    // ---------- generic scalar fallback: maha = || W~ x~ ||^2 ----------
    extern __shared__ char msm[];
    float* sW = (float*)msm;                  // [64*68] fp32 W~ for current k
    __shared__ float s_ck[KK];
    __shared__ float s_wm[9], s_ws[9];
    int tx = threadIdx.x, wid = tx >> 5, lane = tx & 31;
    if (tx < KK) s_ck[tx] = g_ck[tx];

    float xt[65];
    if (tx < 256) {
        const float4* xs = (const float4*)(X + ((size_t)blockIdx.x * 256 + tx) * DD);
#pragma unroll
        for (int i = 0; i < 16; i++) {
            float4 v = xs[i];
            xt[4 * i] = v.x; xt[4 * i + 1] = v.y; xt[4 * i + 2] = v.z; xt[4 * i + 3] = v.w;
        }
        xt[64] = 1.0f;
    }

    float mx = -INFINITY, sm = 0.f;
#pragma unroll 1
    for (int k = 0; k < KK; k++) {
        __syncthreads();
        const float4* src = (const float4*)g_Wf[k];
        for (int i = tx; i < 64 * 68 / 4; i += 288) ((float4*)sW)[i] = src[i];
        __syncthreads();
        if (tx < 256) {
            float maha = 0.f;
            for (int j = 0; j < 64; j++) {
                const float* row = sW + j * 68;
                float z = 0.f;
#pragma unroll
                for (int c = 0; c < 65; c++) z = fmaf(row[c], xt[c], z);
                maha = fmaf(z, z, maha);
            }
            float logp = s_ck[k] - 0.5f * maha;
            if (logp > mx) { sm = fmaf(sm, __expf(mx - logp), 1.0f); mx = logp; }
            else           { sm += __expf(logp - mx); }
        }
    }
    if (tx < 256) {
#pragma unroll
        for (int o = 16; o; o >>= 1) {
            float m2 = __shfl_xor_sync(0xffffffffu, mx, o);
            float s2 = __shfl_xor_sync(0xffffffffu, sm, o);
            float M = fmaxf(mx, m2);
            sm = sm * __expf(mx - M) + s2 * __expf(m2 - M);
            mx = M;
        }
        if (lane == 0) { s_wm[wid] = mx; s_ws[wid] = sm; }
    }
    __syncthreads();
    if (tx < 8) {
        float m = s_wm[tx], s = s_ws[tx];
#pragma unroll
        for (int o = 4; o; o >>= 1) {
            float m2 = __shfl_xor_sync(0xffu, m, o);
            float s2 = __shfl_xor_sync(0xffu, s, o);
            float M = fmaxf(m, m2);
            s = s * __expf(m - M) + s2 * __expf(m2 - M);
            m = M;
        }
        if (tx == 0) { g_rm[blockIdx.x] = m; g_rs[blockIdx.x] = s; }
    }
#endif
}

// ============= final reduce: -logsumexp over 128 CTA partials =============
__global__ void reduce_kernel(float* __restrict__ out) {
    __shared__ float rm[4], rs[4];
    int tx = threadIdx.x, lane = tx & 31, wid = tx >> 5;
    float m = g_rm[tx], s = g_rs[tx];
#pragma unroll
    for (int o = 16; o; o >>= 1) {
        float m2 = __shfl_xor_sync(0xffffffffu, m, o);
        float s2 = __shfl_xor_sync(0xffffffffu, s, o);
        float M = fmaxf(m, m2);
        s = s * __expf(m - M) + s2 * __expf(m2 - M);
        m = M;
    }
    if (lane == 0) { rm[wid] = m; rs[wid] = s; }
    __syncthreads();
    if (tx < 4) {
        float mm = rm[tx], ss = rs[tx];
#pragma unroll
        for (int o = 2; o; o >>= 1) {
            float m2 = __shfl_xor_sync(0xfu, mm, o);
            float s2 = __shfl_xor_sync(0xfu, ss, o);
            float M = fmaxf(mm, m2);
            ss = ss * __expf(mm - M) + s2 * __expf(m2 - M);
            mm = M;
        }
        if (tx == 0) out[0] = -(mm + logf(ss));
    }
}

// ---------------- launch ----------------
extern "C" void kernel_launch(void* const* d_in, const int* in_sizes, int n_in,
                              void* d_out, int out_size) {
    const float* X  = (const float*)d_in[0];
    const float* mu = (const float*)d_in[1];
    const float* L  = (const float*)d_in[2];
    const float* w  = (const float*)d_in[3];
    float* out = (float*)d_out;

    static int attr_done = 0;
    if (!attr_done) {
        cudaFuncSetAttribute(setup_kernel, cudaFuncAttributeMaxDynamicSharedMemorySize, 49664);
        cudaFuncSetAttribute(main_kernel, cudaFuncAttributeMaxDynamicSharedMemorySize, 99328);
        attr_done = 1;
    }

    setup_kernel<<<KK, 512, 49664>>>(L, mu, w);
    main_kernel<<<NPTS / 256, 288, 99328>>>(X);
    reduce_kernel<<<1, 128>>>(out);
}